// round 15
// baseline (speedup 1.0000x reference)
#include <cuda_runtime.h>
#include <cuda_bf16.h>
#include <cuda_fp16.h>
#include <math.h>
#include <stdint.h>

#define BB  8
#define LL  1024
#define DD  1024
#define HH  16
#define DHH 64
#define MM  (BB * LL)

typedef unsigned long long u64;

// ---------------- device-global scratch ----------------
__device__ __nv_bfloat16 g_xh[MM * DD], g_xl[MM * DD];
__device__ __nv_bfloat16 g_wh[4][DD * DD], g_wl[4][DD * DD];  // [Wq,Wk,Wv,Wo]
__device__ __half g_qh[MM * DD];
__device__ __half g_kh[MM * DD], g_kl[MM * DD];
__device__ __half g_vh[MM * DD];
__device__ __nv_bfloat16 g_ah[MM * DD], g_al[MM * DD];
__device__ u64 g_bmask[LL * LL / 64];

// ---------------- PTX helpers ----------------
__device__ __forceinline__ uint32_t s2u(const void* p) {
    uint32_t a;
    asm("{ .reg .u64 t; cvta.to.shared.u64 t, %1; cvt.u32.u64 %0, t; }"
        : "=r"(a) : "l"(p));
    return a;
}
__device__ __forceinline__ void cp16(uint32_t d, const void* s) {
    asm volatile("cp.async.cg.shared.global [%0], [%1], 16;" :: "r"(d), "l"(s));
}
__device__ __forceinline__ void cp_commit() {
    asm volatile("cp.async.commit_group;");
}
template <int N> __device__ __forceinline__ void cp_wait() {
    asm volatile("cp.async.wait_group %0;" :: "n"(N));
}
__device__ __forceinline__ void ldm4(uint32_t& r0, uint32_t& r1,
                                     uint32_t& r2, uint32_t& r3, uint32_t a) {
    asm volatile("ldmatrix.sync.aligned.m8n8.x4.shared.b16 {%0,%1,%2,%3}, [%4];"
                 : "=r"(r0), "=r"(r1), "=r"(r2), "=r"(r3) : "r"(a));
}
__device__ __forceinline__ void ldm4t(uint32_t& r0, uint32_t& r1,
                                      uint32_t& r2, uint32_t& r3, uint32_t a) {
    asm volatile("ldmatrix.sync.aligned.m8n8.x4.trans.shared.b16 {%0,%1,%2,%3}, [%4];"
                 : "=r"(r0), "=r"(r1), "=r"(r2), "=r"(r3) : "r"(a));
}
__device__ __forceinline__ void mma_bf16(float* c, const uint32_t* a,
                                         uint32_t b0, uint32_t b1) {
    asm volatile(
        "mma.sync.aligned.m16n8k16.row.col.f32.bf16.bf16.f32 "
        "{%0,%1,%2,%3}, {%4,%5,%6,%7}, {%8,%9}, {%0,%1,%2,%3};"
        : "+f"(c[0]), "+f"(c[1]), "+f"(c[2]), "+f"(c[3])
        : "r"(a[0]), "r"(a[1]), "r"(a[2]), "r"(a[3]), "r"(b0), "r"(b1));
}
__device__ __forceinline__ void mma_f16(float* c, uint32_t a0, uint32_t a1,
                                        uint32_t a2, uint32_t a3,
                                        uint32_t b0, uint32_t b1) {
    asm volatile(
        "mma.sync.aligned.m16n8k16.row.col.f32.f16.f16.f32 "
        "{%0,%1,%2,%3}, {%4,%5,%6,%7}, {%8,%9}, {%0,%1,%2,%3};"
        : "+f"(c[0]), "+f"(c[1]), "+f"(c[2]), "+f"(c[3])
        : "r"(a0), "r"(a1), "r"(a2), "r"(a3), "r"(b0), "r"(b1));
}
__device__ __forceinline__ float ex2f(float x) {
    float r;
    asm("ex2.approx.ftz.f32 %0, %1;" : "=f"(r) : "f"(x));
    return r;
}
__device__ __forceinline__ uint32_t packh2(float hi, float lo) {
    uint32_t r;
    asm("cvt.rn.f16x2.f32 %0, %1, %2;" : "=r"(r) : "f"(hi), "f"(lo));
    return r;
}
__device__ __forceinline__ float2 h2f2(uint32_t u) {
    __half2 h = *reinterpret_cast<__half2*>(&u);
    return __half22float2(h);
}

// ============================================================
// splits
// ============================================================
__global__ __launch_bounds__(256) void split_kernel(
    const float4* __restrict__ src,
    __nv_bfloat162* __restrict__ hi, __nv_bfloat162* __restrict__ lo, int n4)
{
    int i = blockIdx.x * blockDim.x + threadIdx.x;
    if (i >= n4) return;
    float4 v = src[i];
    __nv_bfloat16 hx = __float2bfloat16(v.x), hy = __float2bfloat16(v.y);
    __nv_bfloat16 hz = __float2bfloat16(v.z), hw = __float2bfloat16(v.w);
    hi[2 * i + 0] = __nv_bfloat162(hx, hy);
    hi[2 * i + 1] = __nv_bfloat162(hz, hw);
    lo[2 * i + 0] = __floats2bfloat162_rn(v.x - __bfloat162float(hx),
                                          v.y - __bfloat162float(hy));
    lo[2 * i + 1] = __floats2bfloat162_rn(v.z - __bfloat162float(hz),
                                          v.w - __bfloat162float(hw));
}

__global__ __launch_bounds__(256) void wsplit_kernel(
    const float4* __restrict__ w0, const float4* __restrict__ w1,
    const float4* __restrict__ w2, const float4* __restrict__ w3,
    __nv_bfloat162* __restrict__ hi, __nv_bfloat162* __restrict__ lo, int n4)
{
    int i = blockIdx.x * blockDim.x + threadIdx.x;
    if (i >= n4) return;
    int sel = blockIdx.y;
    const float4* src = (sel == 0) ? w0 : (sel == 1) ? w1 : (sel == 2) ? w2 : w3;
    size_t base = (size_t)sel * 2 * n4;
    float4 v = src[i];
    __nv_bfloat16 hx = __float2bfloat16(v.x), hy = __float2bfloat16(v.y);
    __nv_bfloat16 hz = __float2bfloat16(v.z), hw = __float2bfloat16(v.w);
    hi[base + 2 * i + 0] = __nv_bfloat162(hx, hy);
    hi[base + 2 * i + 1] = __nv_bfloat162(hz, hw);
    lo[base + 2 * i + 0] = __floats2bfloat162_rn(v.x - __bfloat162float(hx),
                                                 v.y - __bfloat162float(hy));
    lo[base + 2 * i + 1] = __floats2bfloat162_rn(v.z - __bfloat162float(hz),
                                                 v.w - __bfloat162float(hw));
}

// ============================================================
// mask -> 64-bit bitmask per (qb, kb, w, lane), bit = nt*4+j
// ============================================================
__global__ __launch_bounds__(256) void bmask_kernel(
    const float* __restrict__ mask, u64* __restrict__ bm)
{
    int idx = blockIdx.x * blockDim.x + threadIdx.x;
    if (idx >= LL * LL / 64) return;
    int lane = idx & 31, w = (idx >> 5) & 7, kb = (idx >> 8) & 7, qb = idx >> 11;
    u64 bits = 0;
#pragma unroll
    for (int e = 0; e < 64; e++) {
        int nt = e >> 2, j = e & 3;
        int q = qb * 128 + w * 16 + (lane >> 2) + 8 * (j >> 1);
        int k = kb * 128 + nt * 8 + (lane & 3) * 2 + (j & 1);
        if (mask[q * LL + k] != 0.f) bits |= (1ull << e);
    }
    bm[idx] = bits;
}

// ============================================================
// bf16-split GEMM (NT) — frozen r12 structure + m_base offset.
// MODE 0: fp32 out. MODE 1: fused QKV (Qh | Kh+Kl | Vh).
// ============================================================
#define BK 32
#define NKI (DD / BK)
#define MAT_B 8192
#define STG_B (4 * MAT_B)
#define OFF_AH 0
#define OFF_AL MAT_B
#define OFF_BH (2 * MAT_B)
#define OFF_BL (3 * MAT_B)
#define GSMEM (3 * STG_B)   // 98304

__device__ __forceinline__ uint32_t swz(int row, int c) {
    return (uint32_t)(row * 64 + ((c ^ (row & 3)) << 4));
}

__device__ __forceinline__ void g_load_stage(
    uint32_t sbase,
    const __nv_bfloat16* __restrict__ Ah, const __nv_bfloat16* __restrict__ Al,
    const __nv_bfloat16* __restrict__ Bh, const __nv_bfloat16* __restrict__ Bl,
    int m0, int n0, int k0, int tid)
{
    const int r1 = tid >> 2, r2 = r1 + 64, c = tid & 3;
    const int kc = k0 + c * 8;
    const size_t a1 = (size_t)(m0 + r1) * DD + kc;
    const size_t a2 = (size_t)(m0 + r2) * DD + kc;
    const size_t b1 = (size_t)(n0 + r1) * DD + kc;
    const size_t b2 = (size_t)(n0 + r2) * DD + kc;
    const uint32_t s1 = swz(r1, c), s2 = swz(r2, c);
    cp16(sbase + OFF_AH + s1, Ah + a1);
    cp16(sbase + OFF_AH + s2, Ah + a2);
    cp16(sbase + OFF_AL + s1, Al + a1);
    cp16(sbase + OFF_AL + s2, Al + a2);
    cp16(sbase + OFF_BH + s1, Bh + b1);
    cp16(sbase + OFF_BH + s2, Bh + b2);
    cp16(sbase + OFF_BL + s1, Bl + b1);
    cp16(sbase + OFF_BL + s2, Bl + b2);
}

template <int MODE>
__global__ __launch_bounds__(256, 2) void gemm_mma_kernel(
    const __nv_bfloat16* __restrict__ Ah, const __nv_bfloat16* __restrict__ Al,
    const __nv_bfloat16* __restrict__ Bh, const __nv_bfloat16* __restrict__ Bl,
    float* __restrict__ Cf,
    __half* __restrict__ Qh,
    __half* __restrict__ Kh, __half* __restrict__ Kl,
    __half* __restrict__ Vh,
    float scale_q, int m_base)
{
    extern __shared__ char smg[];
    const uint32_t sbase = s2u(smg);
    const int tid = threadIdx.x, wid = tid >> 5, lane = tid & 31;
    const int m0 = m_base + blockIdx.y * 128, n0 = blockIdx.x * 128;
    const int wm0 = (wid & 1) * 64, wn0 = (wid >> 1) * 32;

    float acc[4][4][4];
#pragma unroll
    for (int i = 0; i < 4; i++)
#pragma unroll
        for (int j = 0; j < 4; j++)
#pragma unroll
            for (int r = 0; r < 4; r++) acc[i][j][r] = 0.f;

    const int a_row_l = ((lane >> 3) & 1) * 8 + (lane & 7);
    const int a_cl = lane >> 4;
    const int b_row_l = (lane >> 4) * 8 + (lane & 7);
    const int b_cl = (lane >> 3) & 1;

    g_load_stage(sbase, Ah, Al, Bh, Bl, m0, n0, 0, tid);
    cp_commit();
    g_load_stage(sbase + STG_B, Ah, Al, Bh, Bl, m0, n0, BK, tid);
    cp_commit();

    int s_cur = 0, s_nxt = 2;
    for (int k = 0; k < NKI; k++) {
        cp_wait<1>();
        __syncthreads();
        if (k + 2 < NKI)
            g_load_stage(sbase + s_nxt * STG_B, Ah, Al, Bh, Bl,
                         m0, n0, (k + 2) * BK, tid);
        cp_commit();

        const uint32_t st = sbase + s_cur * STG_B;
#pragma unroll
        for (int kk = 0; kk < 2; kk++) {
            uint32_t ah[4][4], al[4][4], bh[2][4], bl[2][4];
#pragma unroll
            for (int mt = 0; mt < 4; mt++) {
                uint32_t off = swz(wm0 + mt * 16 + a_row_l, kk * 2 + a_cl);
                ldm4(ah[mt][0], ah[mt][1], ah[mt][2], ah[mt][3], st + OFF_AH + off);
                ldm4(al[mt][0], al[mt][1], al[mt][2], al[mt][3], st + OFF_AL + off);
            }
#pragma unroll
            for (int ng = 0; ng < 2; ng++) {
                uint32_t off = swz(wn0 + ng * 16 + b_row_l, kk * 2 + b_cl);
                ldm4(bh[ng][0], bh[ng][1], bh[ng][2], bh[ng][3], st + OFF_BH + off);
                ldm4(bl[ng][0], bl[ng][1], bl[ng][2], bl[ng][3], st + OFF_BL + off);
            }
#pragma unroll
            for (int mt = 0; mt < 4; mt++)
#pragma unroll
                for (int nt = 0; nt < 4; nt++) {
                    const int ng = nt >> 1, hb = (nt & 1) * 2;
                    mma_bf16(acc[mt][nt], ah[mt], bh[ng][hb], bh[ng][hb + 1]);
                    mma_bf16(acc[mt][nt], ah[mt], bl[ng][hb], bl[ng][hb + 1]);
                    mma_bf16(acc[mt][nt], al[mt], bh[ng][hb], bh[ng][hb + 1]);
                }
        }
        s_cur = (s_cur == 2) ? 0 : s_cur + 1;
        s_nxt = (s_nxt == 2) ? 0 : s_nxt + 1;
    }

    const int er = lane >> 2, ec = (lane & 3) * 2;
    if (MODE == 0) {
#pragma unroll
        for (int mt = 0; mt < 4; mt++)
#pragma unroll
            for (int nt = 0; nt < 4; nt++) {
                size_t i0 = (size_t)(m0 + wm0 + mt * 16 + er) * DD
                          + n0 + wn0 + nt * 8 + ec;
                size_t i1 = i0 + 8 * DD;
                *(float2*)(Cf + i0) = make_float2(acc[mt][nt][0], acc[mt][nt][1]);
                *(float2*)(Cf + i1) = make_float2(acc[mt][nt][2], acc[mt][nt][3]);
            }
    } else {
        const int which = n0 >> 10;                 // 0=Q, 1=K, 2=V
        __half* Ch = (which == 0) ? Qh : (which == 1) ? Kh : Vh;
        const float sc = (which == 0) ? scale_q : 1.0f;
        const int nc0 = n0 & 1023;
#pragma unroll
        for (int mt = 0; mt < 4; mt++)
#pragma unroll
            for (int nt = 0; nt < 4; nt++) {
                size_t i0 = (size_t)(m0 + wm0 + mt * 16 + er) * DD
                          + nc0 + wn0 + nt * 8 + ec;
                size_t i1 = i0 + 8 * DD;
                float v0 = acc[mt][nt][0] * sc, v1 = acc[mt][nt][1] * sc;
                float v2 = acc[mt][nt][2] * sc, v3 = acc[mt][nt][3] * sc;
                __half h0 = __float2half_rn(v0), h1 = __float2half_rn(v1);
                __half h2 = __float2half_rn(v2), h3 = __float2half_rn(v3);
                *(__half2*)(Ch + i0) = __half2(h0, h1);
                *(__half2*)(Ch + i1) = __half2(h2, h3);
                if (which == 1) {
                    *(__half2*)(Kl + i0) = __half2(
                        __float2half_rn(v0 - __half2float(h0)),
                        __float2half_rn(v1 - __half2float(h1)));
                    *(__half2*)(Kl + i1) = __half2(
                        __float2half_rn(v2 - __half2float(h2)),
                        __float2half_rn(v3 - __half2float(h3)));
                }
            }
    }
}

// ============================================================
// Tensor-core flash attention — frozen r12 structure + b_base.
// ============================================================
#define A_QH 0
#define A_ST 16384
#define A_STGB 49152
#define A_KH 0
#define A_KL 16384
#define A_VH 32768
#define A_SMEM (A_ST + 2 * A_STGB)   // 114688

__device__ __forceinline__ void a_load_q(
    uint32_t sb, const __half* qh, int b, int q0, int h, int tid)
{
    const int row = tid >> 1, cb = (tid & 1) * 4;
    const size_t base = ((size_t)(b * LL + q0 + row)) * DD + h * DHH;
#pragma unroll
    for (int c = 0; c < 4; c++) {
        int ch = cb + c;
        uint32_t dst = (uint32_t)(row * 128 + ((ch ^ (row & 7)) << 4));
        cp16(sb + A_QH + dst, qh + base + ch * 8);
    }
}
__device__ __forceinline__ void a_load_kv(
    uint32_t stg, const __half* kh, const __half* kl,
    const __half* vh, int b, int k0, int h, int tid)
{
    const int row = tid >> 1, cb = (tid & 1) * 4;
    const size_t base = ((size_t)(b * LL + k0 + row)) * DD + h * DHH;
#pragma unroll
    for (int c = 0; c < 4; c++) {
        int ch = cb + c;
        uint32_t dst = (uint32_t)(row * 128 + ((ch ^ (row & 7)) << 4));
        cp16(stg + A_KH + dst, kh + base + ch * 8);
        cp16(stg + A_KL + dst, kl + base + ch * 8);
        cp16(stg + A_VH + dst, vh + base + ch * 8);
    }
}

__global__ __launch_bounds__(256, 2) void attn_mma_kernel(
    const __half* __restrict__ qh,
    const __half* __restrict__ kh, const __half* __restrict__ kl,
    const __half* __restrict__ vh,
    const u64* __restrict__ bmask,
    __nv_bfloat16* __restrict__ ah, __nv_bfloat16* __restrict__ al,
    int b_base)
{
    extern __shared__ char sma[];
    const uint32_t sb = s2u(sma);
    const int tid = threadIdx.x, lane = tid & 31, w = tid >> 5;
    const int qb = blockIdx.x, h = blockIdx.y, b = b_base + blockIdx.z;
    const int q0 = qb * 128;

    a_load_q(sb, qh, b, q0, h, tid);
    a_load_kv(sb + A_ST, kh, kl, vh, b, 0, h, tid);
    cp_commit();
    cp_wait<0>();
    __syncthreads();

    uint32_t qf[4][4];
    {
        const int arow = w * 16 + ((lane >> 3) & 1) * 8 + (lane & 7);
        const int acl = lane >> 4;
#pragma unroll
        for (int kc = 0; kc < 4; kc++) {
            int ch = kc * 2 + acl;
            uint32_t off = (uint32_t)(arow * 128 + ((ch ^ (arow & 7)) << 4));
            ldm4(qf[kc][0], qf[kc][1], qf[kc][2], qf[kc][3], sb + A_QH + off);
        }
    }

    float acc_o[8][4];
#pragma unroll
    for (int i = 0; i < 8; i++)
#pragma unroll
        for (int j = 0; j < 4; j++) acc_o[i][j] = 0.f;
    float m0r = -1e30f, m1r = -1e30f, l0r = 0.f, l1r = 0.f;

    const u64* bmp = bmask + (size_t)qb * 2048 + w * 32 + lane;
    const int b_row_l = (lane >> 4) * 8 + (lane & 7);
    const int b_cl = (lane >> 3) & 1;
    const int v_row_l = ((lane >> 3) & 1) * 8 + (lane & 7);
    const int v_cl = lane >> 4;

    for (int kb = 0; kb < 8; kb++) {
        cp_wait<0>();
        __syncthreads();
        if (kb + 1 < 8) {
            a_load_kv(sb + A_ST + ((kb + 1) & 1) * A_STGB,
                      kh, kl, vh, b, (kb + 1) * 128, h, tid);
            cp_commit();
        }
        const uint32_t stg = sb + A_ST + (kb & 1) * A_STGB;

        float s[16][4];
#pragma unroll
        for (int i = 0; i < 16; i++)
#pragma unroll
            for (int j = 0; j < 4; j++) s[i][j] = 0.f;

#pragma unroll
        for (int g = 0; g < 8; g++)
#pragma unroll
            for (int kc = 0; kc < 4; kc++) {
                int row = g * 16 + b_row_l, ch = kc * 2 + b_cl;
                uint32_t off = (uint32_t)(row * 128 + ((ch ^ (row & 7)) << 4));
                uint32_t k4h[4], k4l[4];
                ldm4(k4h[0], k4h[1], k4h[2], k4h[3], stg + A_KH + off);
                ldm4(k4l[0], k4l[1], k4l[2], k4l[3], stg + A_KL + off);
                mma_f16(s[2*g],   qf[kc][0], qf[kc][1], qf[kc][2], qf[kc][3], k4h[0], k4h[1]);
                mma_f16(s[2*g+1], qf[kc][0], qf[kc][1], qf[kc][2], qf[kc][3], k4h[2], k4h[3]);
                mma_f16(s[2*g],   qf[kc][0], qf[kc][1], qf[kc][2], qf[kc][3], k4l[0], k4l[1]);
                mma_f16(s[2*g+1], qf[kc][0], qf[kc][1], qf[kc][2], qf[kc][3], k4l[2], k4l[3]);
            }

        const u64 bm = bmp[kb * 256];
        float mx0 = -1e30f, mx1 = -1e30f;
#pragma unroll
        for (int nt = 0; nt < 16; nt++) {
#pragma unroll
            for (int j = 0; j < 4; j++)
                if (!((bm >> (nt * 4 + j)) & 1ull)) s[nt][j] = -1e30f;
            mx0 = fmaxf(mx0, fmaxf(s[nt][0], s[nt][1]));
            mx1 = fmaxf(mx1, fmaxf(s[nt][2], s[nt][3]));
        }
        mx0 = fmaxf(mx0, __shfl_xor_sync(~0u, mx0, 1));
        mx0 = fmaxf(mx0, __shfl_xor_sync(~0u, mx0, 2));
        mx1 = fmaxf(mx1, __shfl_xor_sync(~0u, mx1, 1));
        mx1 = fmaxf(mx1, __shfl_xor_sync(~0u, mx1, 2));
        float mn0 = fmaxf(m0r, mx0), mn1 = fmaxf(m1r, mx1);
        float c0 = ex2f(m0r - mn0), c1 = ex2f(m1r - mn1);
        m0r = mn0; m1r = mn1;

        float ls0 = 0.f, ls1 = 0.f;
#pragma unroll
        for (int nt = 0; nt < 16; nt++) {
            s[nt][0] = ex2f(s[nt][0] - mn0);
            s[nt][1] = ex2f(s[nt][1] - mn0);
            s[nt][2] = ex2f(s[nt][2] - mn1);
            s[nt][3] = ex2f(s[nt][3] - mn1);
            ls0 += s[nt][0] + s[nt][1];
            ls1 += s[nt][2] + s[nt][3];
        }
        ls0 += __shfl_xor_sync(~0u, ls0, 1);
        ls0 += __shfl_xor_sync(~0u, ls0, 2);
        ls1 += __shfl_xor_sync(~0u, ls1, 1);
        ls1 += __shfl_xor_sync(~0u, ls1, 2);
        l0r = l0r * c0 + ls0;
        l1r = l1r * c1 + ls1;
#pragma unroll
        for (int i = 0; i < 8; i++) {
            acc_o[i][0] *= c0; acc_o[i][1] *= c0;
            acc_o[i][2] *= c1; acc_o[i][3] *= c1;
        }

#pragma unroll
        for (int kc = 0; kc < 8; kc++) {
            uint32_t ph0 = packh2(s[2*kc][1],   s[2*kc][0]);
            uint32_t ph1 = packh2(s[2*kc][3],   s[2*kc][2]);
            uint32_t ph2 = packh2(s[2*kc+1][1], s[2*kc+1][0]);
            uint32_t ph3 = packh2(s[2*kc+1][3], s[2*kc+1][2]);
            float2 f0 = h2f2(ph0), f1 = h2f2(ph1), f2 = h2f2(ph2), f3 = h2f2(ph3);
            uint32_t pl0 = packh2(s[2*kc][1] - f0.y,   s[2*kc][0] - f0.x);
            uint32_t pl1 = packh2(s[2*kc][3] - f1.y,   s[2*kc][2] - f1.x);
            uint32_t pl2 = packh2(s[2*kc+1][1] - f2.y, s[2*kc+1][0] - f2.x);
            uint32_t pl3 = packh2(s[2*kc+1][3] - f3.y, s[2*kc+1][2] - f3.x);
            int vrow = kc * 16 + v_row_l;
#pragma unroll
            for (int x4 = 0; x4 < 4; x4++) {
                int ch = x4 * 2 + v_cl;
                uint32_t off = (uint32_t)(vrow * 128 + ((ch ^ (vrow & 7)) << 4));
                uint32_t v4h[4];
                ldm4t(v4h[0], v4h[1], v4h[2], v4h[3], stg + A_VH + off);
                mma_f16(acc_o[2*x4],   ph0, ph1, ph2, ph3, v4h[0], v4h[1]);
                mma_f16(acc_o[2*x4+1], ph0, ph1, ph2, ph3, v4h[2], v4h[3]);
                mma_f16(acc_o[2*x4],   pl0, pl1, pl2, pl3, v4h[0], v4h[1]);
                mma_f16(acc_o[2*x4+1], pl0, pl1, pl2, pl3, v4h[2], v4h[3]);
            }
        }
    }

    const float inv0 = 1.f / l0r, inv1 = 1.f / l1r;
    const int r0 = q0 + w * 16 + (lane >> 2);
#pragma unroll
    for (int nt = 0; nt < 8; nt++) {
        int col = h * DHH + nt * 8 + (lane & 3) * 2;
        size_t i0 = (size_t)(b * LL + r0) * DD + col;
        size_t i1 = i0 + 8 * DD;
        float v0 = acc_o[nt][0] * inv0, v1 = acc_o[nt][1] * inv0;
        float v2 = acc_o[nt][2] * inv1, v3 = acc_o[nt][3] * inv1;
        __nv_bfloat16 h0 = __float2bfloat16(v0), h1 = __float2bfloat16(v1);
        __nv_bfloat16 h2 = __float2bfloat16(v2), h3 = __float2bfloat16(v3);
        *(__nv_bfloat162*)(ah + i0) = __nv_bfloat162(h0, h1);
        *(__nv_bfloat162*)(ah + i1) = __nv_bfloat162(h2, h3);
        *(__nv_bfloat162*)(al + i0) =
            __floats2bfloat162_rn(v0 - __bfloat162float(h0), v1 - __bfloat162float(h1));
        *(__nv_bfloat162*)(al + i1) =
            __floats2bfloat162_rn(v2 - __bfloat162float(h2), v3 - __bfloat162float(h3));
    }
}

// ============================================================
// Launch — half-split pipeline + parallel prelude + priorities
// ============================================================
extern "C" void kernel_launch(void* const* d_in, const int* in_sizes, int n_in,
                              void* d_out, int out_size)
{
    const float* x    = (const float*)d_in[0];
    const float* mask = (const float*)d_in[1];
    const float* Wk   = (const float*)d_in[2];
    const float* Wv   = (const float*)d_in[3];
    const float* Wq   = (const float*)d_in[4];
    const float* Wo   = (const float*)d_in[5];
    float* out = (float*)d_out;

    __nv_bfloat16 *xh, *xl, *ah, *al, *wh, *wl;
    __half *qh, *kh, *kl, *vh;
    u64* bm;
    cudaGetSymbolAddress((void**)&xh, g_xh);
    cudaGetSymbolAddress((void**)&xl, g_xl);
    cudaGetSymbolAddress((void**)&ah, g_ah);
    cudaGetSymbolAddress((void**)&al, g_al);
    cudaGetSymbolAddress((void**)&wh, g_wh);
    cudaGetSymbolAddress((void**)&wl, g_wl);
    cudaGetSymbolAddress((void**)&qh, g_qh);
    cudaGetSymbolAddress((void**)&kh, g_kh);
    cudaGetSymbolAddress((void**)&kl, g_kl);
    cudaGetSymbolAddress((void**)&vh, g_vh);
    cudaGetSymbolAddress((void**)&bm, g_bmask);

    static int init_done = 0;
    static cudaStream_t sQ, sA, sW;
    static cudaEvent_t evFork, evX, evQ[2], evA[2], evJoin;
    if (!init_done) {
        cudaFuncSetAttribute(gemm_mma_kernel<0>,
                             cudaFuncAttributeMaxDynamicSharedMemorySize, GSMEM);
        cudaFuncSetAttribute(gemm_mma_kernel<1>,
                             cudaFuncAttributeMaxDynamicSharedMemorySize, GSMEM);
        cudaFuncSetAttribute(attn_mma_kernel,
                             cudaFuncAttributeMaxDynamicSharedMemorySize, A_SMEM);
        int prLo, prHi;   // prLo = least priority (numerically greatest)
        cudaDeviceGetStreamPriorityRange(&prLo, &prHi);
        cudaStreamCreateWithPriority(&sQ, cudaStreamNonBlocking, prLo);  // low
        cudaStreamCreateWithPriority(&sA, cudaStreamNonBlocking, prHi);  // high
        cudaStreamCreateWithPriority(&sW, cudaStreamNonBlocking, prHi);  // high
        cudaEventCreateWithFlags(&evFork, cudaEventDisableTiming);
        cudaEventCreateWithFlags(&evX, cudaEventDisableTiming);
        cudaEventCreateWithFlags(&evJoin, cudaEventDisableTiming);
        for (int hlf = 0; hlf < 2; hlf++) {
            cudaEventCreateWithFlags(&evQ[hlf], cudaEventDisableTiming);
            cudaEventCreateWithFlags(&evA[hlf], cudaEventDisableTiming);
        }
        init_done = 1;
    }

    const float SCALE_Q = 0.125f * 1.44269504088896341f;

    // fork immediately; prelude runs in parallel across streams
    cudaEventRecord(evFork, 0);
    cudaStreamWaitEvent(sQ, evFork, 0);
    cudaStreamWaitEvent(sA, evFork, 0);
    cudaStreamWaitEvent(sW, evFork, 0);

    {
        // wsplit on sQ (QKV's own stream: in-order dependency, no event)
        int w4 = DD * DD / 4;
        dim3 wgrid((w4 + 255) / 256, 4);
        wsplit_kernel<<<wgrid, 256, 0, sQ>>>(
            (const float4*)Wq, (const float4*)Wk, (const float4*)Wv,
            (const float4*)Wo, (__nv_bfloat162*)wh, (__nv_bfloat162*)wl, w4);
        // split_x on sW, concurrent with wsplit
        int n4 = MM * DD / 4;
        split_kernel<<<(n4 + 255) / 256, 256, 0, sW>>>(
            (const float4*)x, (__nv_bfloat162*)xh, (__nv_bfloat162*)xl, n4);
        cudaEventRecord(evX, sW);
        // bmask on sA (in-order before the attn launches on sA)
        bmask_kernel<<<(LL * LL / 64) / 256, 256, 0, sA>>>(mask, bm);
        // QKV needs split_x too
        cudaStreamWaitEvent(sQ, evX, 0);
    }

    const int HB = BB / 2;                       // 4 batches per half
    dim3 qkv_grid(3 * DD / 128, HB * LL / 128);  // (24, 32)
    dim3 a_grid(LL / 128, HH, HB);               // (8, 16, 4)
    dim3 o_grid(DD / 128, HB * LL / 128);        // (8, 32)

    for (int hlf = 0; hlf < 2; hlf++) {
        const int mb = hlf * HB * LL;
        gemm_mma_kernel<1><<<qkv_grid, 256, GSMEM, sQ>>>(
            xh, xl, wh, wl, nullptr, qh, kh, kl, vh, SCALE_Q, mb);
        cudaEventRecord(evQ[hlf], sQ);

        cudaStreamWaitEvent(sA, evQ[hlf], 0);
        attn_mma_kernel<<<a_grid, 256, A_SMEM, sA>>>(
            qh, kh, kl, vh, bm, ah, al, hlf * HB);
        cudaEventRecord(evA[hlf], sA);

        cudaStreamWaitEvent(sW, evA[hlf], 0);
        gemm_mma_kernel<0><<<o_grid, 256, GSMEM, sW>>>(
            ah, al, wh + (size_t)3 * DD * DD, wl + (size_t)3 * DD * DD,
            out, nullptr, nullptr, nullptr, nullptr, 1.0f, mb);
    }

    // join
    cudaEventRecord(evJoin, sW);
    cudaStreamWaitEvent(0, evJoin, 0);
}

// round 16
// speedup vs baseline: 1.0004x; 1.0004x over previous
#include <cuda_runtime.h>
#include <cuda_bf16.h>
#include <cuda_fp16.h>
#include <math.h>
#include <stdint.h>

#define BB  8
#define LL  1024
#define DD  1024
#define HH  16
#define DHH 64
#define MM  (BB * LL)

typedef unsigned long long u64;

// ---------------- device-global scratch ----------------
__device__ __nv_bfloat16 g_xh[MM * DD], g_xl[MM * DD];
__device__ __nv_bfloat16 g_wh[4][DD * DD], g_wl[4][DD * DD];  // [Wq,Wk,Wv,Wo]
__device__ __half g_qh[MM * DD];
__device__ __half g_kh[MM * DD], g_kl[MM * DD];
__device__ __half g_vh[MM * DD];
__device__ __nv_bfloat16 g_ah[MM * DD], g_al[MM * DD];
__device__ u64 g_bmask[LL * LL / 64];

// ---------------- PTX helpers ----------------
__device__ __forceinline__ uint32_t s2u(const void* p) {
    uint32_t a;
    asm("{ .reg .u64 t; cvta.to.shared.u64 t, %1; cvt.u32.u64 %0, t; }"
        : "=r"(a) : "l"(p));
    return a;
}
__device__ __forceinline__ void cp16(uint32_t d, const void* s) {
    asm volatile("cp.async.cg.shared.global [%0], [%1], 16;" :: "r"(d), "l"(s));
}
__device__ __forceinline__ void cp_commit() {
    asm volatile("cp.async.commit_group;");
}
template <int N> __device__ __forceinline__ void cp_wait() {
    asm volatile("cp.async.wait_group %0;" :: "n"(N));
}
__device__ __forceinline__ void ldm4(uint32_t& r0, uint32_t& r1,
                                     uint32_t& r2, uint32_t& r3, uint32_t a) {
    asm volatile("ldmatrix.sync.aligned.m8n8.x4.shared.b16 {%0,%1,%2,%3}, [%4];"
                 : "=r"(r0), "=r"(r1), "=r"(r2), "=r"(r3) : "r"(a));
}
__device__ __forceinline__ void ldm4t(uint32_t& r0, uint32_t& r1,
                                      uint32_t& r2, uint32_t& r3, uint32_t a) {
    asm volatile("ldmatrix.sync.aligned.m8n8.x4.trans.shared.b16 {%0,%1,%2,%3}, [%4];"
                 : "=r"(r0), "=r"(r1), "=r"(r2), "=r"(r3) : "r"(a));
}
__device__ __forceinline__ void mma_bf16(float* c, const uint32_t* a,
                                         uint32_t b0, uint32_t b1) {
    asm volatile(
        "mma.sync.aligned.m16n8k16.row.col.f32.bf16.bf16.f32 "
        "{%0,%1,%2,%3}, {%4,%5,%6,%7}, {%8,%9}, {%0,%1,%2,%3};"
        : "+f"(c[0]), "+f"(c[1]), "+f"(c[2]), "+f"(c[3])
        : "r"(a[0]), "r"(a[1]), "r"(a[2]), "r"(a[3]), "r"(b0), "r"(b1));
}
__device__ __forceinline__ void mma_f16(float* c, uint32_t a0, uint32_t a1,
                                        uint32_t a2, uint32_t a3,
                                        uint32_t b0, uint32_t b1) {
    asm volatile(
        "mma.sync.aligned.m16n8k16.row.col.f32.f16.f16.f32 "
        "{%0,%1,%2,%3}, {%4,%5,%6,%7}, {%8,%9}, {%0,%1,%2,%3};"
        : "+f"(c[0]), "+f"(c[1]), "+f"(c[2]), "+f"(c[3])
        : "r"(a0), "r"(a1), "r"(a2), "r"(a3), "r"(b0), "r"(b1));
}
__device__ __forceinline__ float ex2f(float x) {
    float r;
    asm("ex2.approx.ftz.f32 %0, %1;" : "=f"(r) : "f"(x));
    return r;
}
__device__ __forceinline__ uint32_t packh2(float hi, float lo) {
    uint32_t r;
    asm("cvt.rn.f16x2.f32 %0, %1, %2;" : "=r"(r) : "f"(hi), "f"(lo));
    return r;
}
__device__ __forceinline__ float2 h2f2(uint32_t u) {
    __half2 h = *reinterpret_cast<__half2*>(&u);
    return __half22float2(h);
}

// ============================================================
// splits
// ============================================================
__global__ __launch_bounds__(256) void split_kernel(
    const float4* __restrict__ src,
    __nv_bfloat162* __restrict__ hi, __nv_bfloat162* __restrict__ lo, int n4)
{
    int i = blockIdx.x * blockDim.x + threadIdx.x;
    if (i >= n4) return;
    float4 v = src[i];
    __nv_bfloat16 hx = __float2bfloat16(v.x), hy = __float2bfloat16(v.y);
    __nv_bfloat16 hz = __float2bfloat16(v.z), hw = __float2bfloat16(v.w);
    hi[2 * i + 0] = __nv_bfloat162(hx, hy);
    hi[2 * i + 1] = __nv_bfloat162(hz, hw);
    lo[2 * i + 0] = __floats2bfloat162_rn(v.x - __bfloat162float(hx),
                                          v.y - __bfloat162float(hy));
    lo[2 * i + 1] = __floats2bfloat162_rn(v.z - __bfloat162float(hz),
                                          v.w - __bfloat162float(hw));
}

__global__ __launch_bounds__(256) void wsplit_kernel(
    const float4* __restrict__ w0, const float4* __restrict__ w1,
    const float4* __restrict__ w2, const float4* __restrict__ w3,
    __nv_bfloat162* __restrict__ hi, __nv_bfloat162* __restrict__ lo, int n4)
{
    int i = blockIdx.x * blockDim.x + threadIdx.x;
    if (i >= n4) return;
    int sel = blockIdx.y;
    const float4* src = (sel == 0) ? w0 : (sel == 1) ? w1 : (sel == 2) ? w2 : w3;
    size_t base = (size_t)sel * 2 * n4;
    float4 v = src[i];
    __nv_bfloat16 hx = __float2bfloat16(v.x), hy = __float2bfloat16(v.y);
    __nv_bfloat16 hz = __float2bfloat16(v.z), hw = __float2bfloat16(v.w);
    hi[base + 2 * i + 0] = __nv_bfloat162(hx, hy);
    hi[base + 2 * i + 1] = __nv_bfloat162(hz, hw);
    lo[base + 2 * i + 0] = __floats2bfloat162_rn(v.x - __bfloat162float(hx),
                                                 v.y - __bfloat162float(hy));
    lo[base + 2 * i + 1] = __floats2bfloat162_rn(v.z - __bfloat162float(hz),
                                                 v.w - __bfloat162float(hw));
}

// ============================================================
// mask -> 64-bit bitmask per (qb, kb, w, lane), bit = nt*4+j
// ============================================================
__global__ __launch_bounds__(256) void bmask_kernel(
    const float* __restrict__ mask, u64* __restrict__ bm)
{
    int idx = blockIdx.x * blockDim.x + threadIdx.x;
    if (idx >= LL * LL / 64) return;
    int lane = idx & 31, w = (idx >> 5) & 7, kb = (idx >> 8) & 7, qb = idx >> 11;
    u64 bits = 0;
#pragma unroll
    for (int e = 0; e < 64; e++) {
        int nt = e >> 2, j = e & 3;
        int q = qb * 128 + w * 16 + (lane >> 2) + 8 * (j >> 1);
        int k = kb * 128 + nt * 8 + (lane & 3) * 2 + (j & 1);
        if (mask[q * LL + k] != 0.f) bits |= (1ull << e);
    }
    bm[idx] = bits;
}

// ============================================================
// bf16-split GEMM (NT) — frozen r12 structure + m_base offset.
// MODE 0: fp32 out. MODE 1: fused QKV (Qh | Kh+Kl | Vh).
// ============================================================
#define BK 32
#define NKI (DD / BK)
#define MAT_B 8192
#define STG_B (4 * MAT_B)
#define OFF_AH 0
#define OFF_AL MAT_B
#define OFF_BH (2 * MAT_B)
#define OFF_BL (3 * MAT_B)
#define GSMEM (3 * STG_B)   // 98304

__device__ __forceinline__ uint32_t swz(int row, int c) {
    return (uint32_t)(row * 64 + ((c ^ (row & 3)) << 4));
}

__device__ __forceinline__ void g_load_stage(
    uint32_t sbase,
    const __nv_bfloat16* __restrict__ Ah, const __nv_bfloat16* __restrict__ Al,
    const __nv_bfloat16* __restrict__ Bh, const __nv_bfloat16* __restrict__ Bl,
    int m0, int n0, int k0, int tid)
{
    const int r1 = tid >> 2, r2 = r1 + 64, c = tid & 3;
    const int kc = k0 + c * 8;
    const size_t a1 = (size_t)(m0 + r1) * DD + kc;
    const size_t a2 = (size_t)(m0 + r2) * DD + kc;
    const size_t b1 = (size_t)(n0 + r1) * DD + kc;
    const size_t b2 = (size_t)(n0 + r2) * DD + kc;
    const uint32_t s1 = swz(r1, c), s2 = swz(r2, c);
    cp16(sbase + OFF_AH + s1, Ah + a1);
    cp16(sbase + OFF_AH + s2, Ah + a2);
    cp16(sbase + OFF_AL + s1, Al + a1);
    cp16(sbase + OFF_AL + s2, Al + a2);
    cp16(sbase + OFF_BH + s1, Bh + b1);
    cp16(sbase + OFF_BH + s2, Bh + b2);
    cp16(sbase + OFF_BL + s1, Bl + b1);
    cp16(sbase + OFF_BL + s2, Bl + b2);
}

template <int MODE>
__global__ __launch_bounds__(256, 2) void gemm_mma_kernel(
    const __nv_bfloat16* __restrict__ Ah, const __nv_bfloat16* __restrict__ Al,
    const __nv_bfloat16* __restrict__ Bh, const __nv_bfloat16* __restrict__ Bl,
    float* __restrict__ Cf,
    __half* __restrict__ Qh,
    __half* __restrict__ Kh, __half* __restrict__ Kl,
    __half* __restrict__ Vh,
    float scale_q, int m_base)
{
    extern __shared__ char smg[];
    const uint32_t sbase = s2u(smg);
    const int tid = threadIdx.x, wid = tid >> 5, lane = tid & 31;
    const int m0 = m_base + blockIdx.y * 128, n0 = blockIdx.x * 128;
    const int wm0 = (wid & 1) * 64, wn0 = (wid >> 1) * 32;

    float acc[4][4][4];
#pragma unroll
    for (int i = 0; i < 4; i++)
#pragma unroll
        for (int j = 0; j < 4; j++)
#pragma unroll
            for (int r = 0; r < 4; r++) acc[i][j][r] = 0.f;

    const int a_row_l = ((lane >> 3) & 1) * 8 + (lane & 7);
    const int a_cl = lane >> 4;
    const int b_row_l = (lane >> 4) * 8 + (lane & 7);
    const int b_cl = (lane >> 3) & 1;

    g_load_stage(sbase, Ah, Al, Bh, Bl, m0, n0, 0, tid);
    cp_commit();
    g_load_stage(sbase + STG_B, Ah, Al, Bh, Bl, m0, n0, BK, tid);
    cp_commit();

    int s_cur = 0, s_nxt = 2;
    for (int k = 0; k < NKI; k++) {
        cp_wait<1>();
        __syncthreads();
        if (k + 2 < NKI)
            g_load_stage(sbase + s_nxt * STG_B, Ah, Al, Bh, Bl,
                         m0, n0, (k + 2) * BK, tid);
        cp_commit();

        const uint32_t st = sbase + s_cur * STG_B;
#pragma unroll
        for (int kk = 0; kk < 2; kk++) {
            uint32_t ah[4][4], al[4][4], bh[2][4], bl[2][4];
#pragma unroll
            for (int mt = 0; mt < 4; mt++) {
                uint32_t off = swz(wm0 + mt * 16 + a_row_l, kk * 2 + a_cl);
                ldm4(ah[mt][0], ah[mt][1], ah[mt][2], ah[mt][3], st + OFF_AH + off);
                ldm4(al[mt][0], al[mt][1], al[mt][2], al[mt][3], st + OFF_AL + off);
            }
#pragma unroll
            for (int ng = 0; ng < 2; ng++) {
                uint32_t off = swz(wn0 + ng * 16 + b_row_l, kk * 2 + b_cl);
                ldm4(bh[ng][0], bh[ng][1], bh[ng][2], bh[ng][3], st + OFF_BH + off);
                ldm4(bl[ng][0], bl[ng][1], bl[ng][2], bl[ng][3], st + OFF_BL + off);
            }
#pragma unroll
            for (int mt = 0; mt < 4; mt++)
#pragma unroll
                for (int nt = 0; nt < 4; nt++) {
                    const int ng = nt >> 1, hb = (nt & 1) * 2;
                    mma_bf16(acc[mt][nt], ah[mt], bh[ng][hb], bh[ng][hb + 1]);
                    mma_bf16(acc[mt][nt], ah[mt], bl[ng][hb], bl[ng][hb + 1]);
                    mma_bf16(acc[mt][nt], al[mt], bh[ng][hb], bh[ng][hb + 1]);
                }
        }
        s_cur = (s_cur == 2) ? 0 : s_cur + 1;
        s_nxt = (s_nxt == 2) ? 0 : s_nxt + 1;
    }

    const int er = lane >> 2, ec = (lane & 3) * 2;
    if (MODE == 0) {
#pragma unroll
        for (int mt = 0; mt < 4; mt++)
#pragma unroll
            for (int nt = 0; nt < 4; nt++) {
                size_t i0 = (size_t)(m0 + wm0 + mt * 16 + er) * DD
                          + n0 + wn0 + nt * 8 + ec;
                size_t i1 = i0 + 8 * DD;
                *(float2*)(Cf + i0) = make_float2(acc[mt][nt][0], acc[mt][nt][1]);
                *(float2*)(Cf + i1) = make_float2(acc[mt][nt][2], acc[mt][nt][3]);
            }
    } else {
        const int which = n0 >> 10;                 // 0=Q, 1=K, 2=V
        __half* Ch = (which == 0) ? Qh : (which == 1) ? Kh : Vh;
        const float sc = (which == 0) ? scale_q : 1.0f;
        const int nc0 = n0 & 1023;
#pragma unroll
        for (int mt = 0; mt < 4; mt++)
#pragma unroll
            for (int nt = 0; nt < 4; nt++) {
                size_t i0 = (size_t)(m0 + wm0 + mt * 16 + er) * DD
                          + nc0 + wn0 + nt * 8 + ec;
                size_t i1 = i0 + 8 * DD;
                float v0 = acc[mt][nt][0] * sc, v1 = acc[mt][nt][1] * sc;
                float v2 = acc[mt][nt][2] * sc, v3 = acc[mt][nt][3] * sc;
                __half h0 = __float2half_rn(v0), h1 = __float2half_rn(v1);
                __half h2 = __float2half_rn(v2), h3 = __float2half_rn(v3);
                *(__half2*)(Ch + i0) = __half2(h0, h1);
                *(__half2*)(Ch + i1) = __half2(h2, h3);
                if (which == 1) {
                    *(__half2*)(Kl + i0) = __half2(
                        __float2half_rn(v0 - __half2float(h0)),
                        __float2half_rn(v1 - __half2float(h1)));
                    *(__half2*)(Kl + i1) = __half2(
                        __float2half_rn(v2 - __half2float(h2)),
                        __float2half_rn(v3 - __half2float(h3)));
                }
            }
    }
}

// ============================================================
// Tensor-core flash attention — frozen r12 structure + b_base.
// ============================================================
#define A_QH 0
#define A_ST 16384
#define A_STGB 49152
#define A_KH 0
#define A_KL 16384
#define A_VH 32768
#define A_SMEM (A_ST + 2 * A_STGB)   // 114688

__device__ __forceinline__ void a_load_q(
    uint32_t sb, const __half* qh, int b, int q0, int h, int tid)
{
    const int row = tid >> 1, cb = (tid & 1) * 4;
    const size_t base = ((size_t)(b * LL + q0 + row)) * DD + h * DHH;
#pragma unroll
    for (int c = 0; c < 4; c++) {
        int ch = cb + c;
        uint32_t dst = (uint32_t)(row * 128 + ((ch ^ (row & 7)) << 4));
        cp16(sb + A_QH + dst, qh + base + ch * 8);
    }
}
__device__ __forceinline__ void a_load_kv(
    uint32_t stg, const __half* kh, const __half* kl,
    const __half* vh, int b, int k0, int h, int tid)
{
    const int row = tid >> 1, cb = (tid & 1) * 4;
    const size_t base = ((size_t)(b * LL + k0 + row)) * DD + h * DHH;
#pragma unroll
    for (int c = 0; c < 4; c++) {
        int ch = cb + c;
        uint32_t dst = (uint32_t)(row * 128 + ((ch ^ (row & 7)) << 4));
        cp16(stg + A_KH + dst, kh + base + ch * 8);
        cp16(stg + A_KL + dst, kl + base + ch * 8);
        cp16(stg + A_VH + dst, vh + base + ch * 8);
    }
}

__global__ __launch_bounds__(256, 2) void attn_mma_kernel(
    const __half* __restrict__ qh,
    const __half* __restrict__ kh, const __half* __restrict__ kl,
    const __half* __restrict__ vh,
    const u64* __restrict__ bmask,
    __nv_bfloat16* __restrict__ ah, __nv_bfloat16* __restrict__ al,
    int b_base)
{
    extern __shared__ char sma[];
    const uint32_t sb = s2u(sma);
    const int tid = threadIdx.x, lane = tid & 31, w = tid >> 5;
    const int qb = blockIdx.x, h = blockIdx.y, b = b_base + blockIdx.z;
    const int q0 = qb * 128;

    a_load_q(sb, qh, b, q0, h, tid);
    a_load_kv(sb + A_ST, kh, kl, vh, b, 0, h, tid);
    cp_commit();
    cp_wait<0>();
    __syncthreads();

    uint32_t qf[4][4];
    {
        const int arow = w * 16 + ((lane >> 3) & 1) * 8 + (lane & 7);
        const int acl = lane >> 4;
#pragma unroll
        for (int kc = 0; kc < 4; kc++) {
            int ch = kc * 2 + acl;
            uint32_t off = (uint32_t)(arow * 128 + ((ch ^ (arow & 7)) << 4));
            ldm4(qf[kc][0], qf[kc][1], qf[kc][2], qf[kc][3], sb + A_QH + off);
        }
    }

    float acc_o[8][4];
#pragma unroll
    for (int i = 0; i < 8; i++)
#pragma unroll
        for (int j = 0; j < 4; j++) acc_o[i][j] = 0.f;
    float m0r = -1e30f, m1r = -1e30f, l0r = 0.f, l1r = 0.f;

    const u64* bmp = bmask + (size_t)qb * 2048 + w * 32 + lane;
    const int b_row_l = (lane >> 4) * 8 + (lane & 7);
    const int b_cl = (lane >> 3) & 1;
    const int v_row_l = ((lane >> 3) & 1) * 8 + (lane & 7);
    const int v_cl = lane >> 4;

    for (int kb = 0; kb < 8; kb++) {
        cp_wait<0>();
        __syncthreads();
        if (kb + 1 < 8) {
            a_load_kv(sb + A_ST + ((kb + 1) & 1) * A_STGB,
                      kh, kl, vh, b, (kb + 1) * 128, h, tid);
            cp_commit();
        }
        const uint32_t stg = sb + A_ST + (kb & 1) * A_STGB;

        float s[16][4];
#pragma unroll
        for (int i = 0; i < 16; i++)
#pragma unroll
            for (int j = 0; j < 4; j++) s[i][j] = 0.f;

#pragma unroll
        for (int g = 0; g < 8; g++)
#pragma unroll
            for (int kc = 0; kc < 4; kc++) {
                int row = g * 16 + b_row_l, ch = kc * 2 + b_cl;
                uint32_t off = (uint32_t)(row * 128 + ((ch ^ (row & 7)) << 4));
                uint32_t k4h[4], k4l[4];
                ldm4(k4h[0], k4h[1], k4h[2], k4h[3], stg + A_KH + off);
                ldm4(k4l[0], k4l[1], k4l[2], k4l[3], stg + A_KL + off);
                mma_f16(s[2*g],   qf[kc][0], qf[kc][1], qf[kc][2], qf[kc][3], k4h[0], k4h[1]);
                mma_f16(s[2*g+1], qf[kc][0], qf[kc][1], qf[kc][2], qf[kc][3], k4h[2], k4h[3]);
                mma_f16(s[2*g],   qf[kc][0], qf[kc][1], qf[kc][2], qf[kc][3], k4l[0], k4l[1]);
                mma_f16(s[2*g+1], qf[kc][0], qf[kc][1], qf[kc][2], qf[kc][3], k4l[2], k4l[3]);
            }

        const u64 bm = bmp[kb * 256];
        float mx0 = -1e30f, mx1 = -1e30f;
#pragma unroll
        for (int nt = 0; nt < 16; nt++) {
#pragma unroll
            for (int j = 0; j < 4; j++)
                if (!((bm >> (nt * 4 + j)) & 1ull)) s[nt][j] = -1e30f;
            mx0 = fmaxf(mx0, fmaxf(s[nt][0], s[nt][1]));
            mx1 = fmaxf(mx1, fmaxf(s[nt][2], s[nt][3]));
        }
        mx0 = fmaxf(mx0, __shfl_xor_sync(~0u, mx0, 1));
        mx0 = fmaxf(mx0, __shfl_xor_sync(~0u, mx0, 2));
        mx1 = fmaxf(mx1, __shfl_xor_sync(~0u, mx1, 1));
        mx1 = fmaxf(mx1, __shfl_xor_sync(~0u, mx1, 2));
        float mn0 = fmaxf(m0r, mx0), mn1 = fmaxf(m1r, mx1);
        float c0 = ex2f(m0r - mn0), c1 = ex2f(m1r - mn1);
        m0r = mn0; m1r = mn1;

        float ls0 = 0.f, ls1 = 0.f;
#pragma unroll
        for (int nt = 0; nt < 16; nt++) {
            s[nt][0] = ex2f(s[nt][0] - mn0);
            s[nt][1] = ex2f(s[nt][1] - mn0);
            s[nt][2] = ex2f(s[nt][2] - mn1);
            s[nt][3] = ex2f(s[nt][3] - mn1);
            ls0 += s[nt][0] + s[nt][1];
            ls1 += s[nt][2] + s[nt][3];
        }
        ls0 += __shfl_xor_sync(~0u, ls0, 1);
        ls0 += __shfl_xor_sync(~0u, ls0, 2);
        ls1 += __shfl_xor_sync(~0u, ls1, 1);
        ls1 += __shfl_xor_sync(~0u, ls1, 2);
        l0r = l0r * c0 + ls0;
        l1r = l1r * c1 + ls1;
#pragma unroll
        for (int i = 0; i < 8; i++) {
            acc_o[i][0] *= c0; acc_o[i][1] *= c0;
            acc_o[i][2] *= c1; acc_o[i][3] *= c1;
        }

#pragma unroll
        for (int kc = 0; kc < 8; kc++) {
            uint32_t ph0 = packh2(s[2*kc][1],   s[2*kc][0]);
            uint32_t ph1 = packh2(s[2*kc][3],   s[2*kc][2]);
            uint32_t ph2 = packh2(s[2*kc+1][1], s[2*kc+1][0]);
            uint32_t ph3 = packh2(s[2*kc+1][3], s[2*kc+1][2]);
            float2 f0 = h2f2(ph0), f1 = h2f2(ph1), f2 = h2f2(ph2), f3 = h2f2(ph3);
            uint32_t pl0 = packh2(s[2*kc][1] - f0.y,   s[2*kc][0] - f0.x);
            uint32_t pl1 = packh2(s[2*kc][3] - f1.y,   s[2*kc][2] - f1.x);
            uint32_t pl2 = packh2(s[2*kc+1][1] - f2.y, s[2*kc+1][0] - f2.x);
            uint32_t pl3 = packh2(s[2*kc+1][3] - f3.y, s[2*kc+1][2] - f3.x);
            int vrow = kc * 16 + v_row_l;
#pragma unroll
            for (int x4 = 0; x4 < 4; x4++) {
                int ch = x4 * 2 + v_cl;
                uint32_t off = (uint32_t)(vrow * 128 + ((ch ^ (vrow & 7)) << 4));
                uint32_t v4h[4];
                ldm4t(v4h[0], v4h[1], v4h[2], v4h[3], stg + A_VH + off);
                mma_f16(acc_o[2*x4],   ph0, ph1, ph2, ph3, v4h[0], v4h[1]);
                mma_f16(acc_o[2*x4+1], ph0, ph1, ph2, ph3, v4h[2], v4h[3]);
                mma_f16(acc_o[2*x4],   pl0, pl1, pl2, pl3, v4h[0], v4h[1]);
                mma_f16(acc_o[2*x4+1], pl0, pl1, pl2, pl3, v4h[2], v4h[3]);
            }
        }
    }

    const float inv0 = 1.f / l0r, inv1 = 1.f / l1r;
    const int r0 = q0 + w * 16 + (lane >> 2);
#pragma unroll
    for (int nt = 0; nt < 8; nt++) {
        int col = h * DHH + nt * 8 + (lane & 3) * 2;
        size_t i0 = (size_t)(b * LL + r0) * DD + col;
        size_t i1 = i0 + 8 * DD;
        float v0 = acc_o[nt][0] * inv0, v1 = acc_o[nt][1] * inv0;
        float v2 = acc_o[nt][2] * inv1, v3 = acc_o[nt][3] * inv1;
        __nv_bfloat16 h0 = __float2bfloat16(v0), h1 = __float2bfloat16(v1);
        __nv_bfloat16 h2 = __float2bfloat16(v2), h3 = __float2bfloat16(v3);
        *(__nv_bfloat162*)(ah + i0) = __nv_bfloat162(h0, h1);
        *(__nv_bfloat162*)(ah + i1) = __nv_bfloat162(h2, h3);
        *(__nv_bfloat162*)(al + i0) =
            __floats2bfloat162_rn(v0 - __bfloat162float(h0), v1 - __bfloat162float(h1));
        *(__nv_bfloat162*)(al + i1) =
            __floats2bfloat162_rn(v2 - __bfloat162float(h2), v3 - __bfloat162float(h3));
    }
}

// ============================================================
// Launch — half-split pipeline (r14) + parallel prelude,
// EQUAL stream priorities (r15's priority experiment reverted)
// ============================================================
extern "C" void kernel_launch(void* const* d_in, const int* in_sizes, int n_in,
                              void* d_out, int out_size)
{
    const float* x    = (const float*)d_in[0];
    const float* mask = (const float*)d_in[1];
    const float* Wk   = (const float*)d_in[2];
    const float* Wv   = (const float*)d_in[3];
    const float* Wq   = (const float*)d_in[4];
    const float* Wo   = (const float*)d_in[5];
    float* out = (float*)d_out;

    __nv_bfloat16 *xh, *xl, *ah, *al, *wh, *wl;
    __half *qh, *kh, *kl, *vh;
    u64* bm;
    cudaGetSymbolAddress((void**)&xh, g_xh);
    cudaGetSymbolAddress((void**)&xl, g_xl);
    cudaGetSymbolAddress((void**)&ah, g_ah);
    cudaGetSymbolAddress((void**)&al, g_al);
    cudaGetSymbolAddress((void**)&wh, g_wh);
    cudaGetSymbolAddress((void**)&wl, g_wl);
    cudaGetSymbolAddress((void**)&qh, g_qh);
    cudaGetSymbolAddress((void**)&kh, g_kh);
    cudaGetSymbolAddress((void**)&kl, g_kl);
    cudaGetSymbolAddress((void**)&vh, g_vh);
    cudaGetSymbolAddress((void**)&bm, g_bmask);

    static int init_done = 0;
    static cudaStream_t sQ, sA, sW;
    static cudaEvent_t evFork, evX, evQ[2], evA[2], evJoin;
    if (!init_done) {
        cudaFuncSetAttribute(gemm_mma_kernel<0>,
                             cudaFuncAttributeMaxDynamicSharedMemorySize, GSMEM);
        cudaFuncSetAttribute(gemm_mma_kernel<1>,
                             cudaFuncAttributeMaxDynamicSharedMemorySize, GSMEM);
        cudaFuncSetAttribute(attn_mma_kernel,
                             cudaFuncAttributeMaxDynamicSharedMemorySize, A_SMEM);
        cudaStreamCreateWithFlags(&sQ, cudaStreamNonBlocking);
        cudaStreamCreateWithFlags(&sA, cudaStreamNonBlocking);
        cudaStreamCreateWithFlags(&sW, cudaStreamNonBlocking);
        cudaEventCreateWithFlags(&evFork, cudaEventDisableTiming);
        cudaEventCreateWithFlags(&evX, cudaEventDisableTiming);
        cudaEventCreateWithFlags(&evJoin, cudaEventDisableTiming);
        for (int hlf = 0; hlf < 2; hlf++) {
            cudaEventCreateWithFlags(&evQ[hlf], cudaEventDisableTiming);
            cudaEventCreateWithFlags(&evA[hlf], cudaEventDisableTiming);
        }
        init_done = 1;
    }

    const float SCALE_Q = 0.125f * 1.44269504088896341f;

    // fork immediately; prelude runs in parallel across streams
    cudaEventRecord(evFork, 0);
    cudaStreamWaitEvent(sQ, evFork, 0);
    cudaStreamWaitEvent(sA, evFork, 0);
    cudaStreamWaitEvent(sW, evFork, 0);

    {
        // wsplit on sQ (in-order before QKV)
        int w4 = DD * DD / 4;
        dim3 wgrid((w4 + 255) / 256, 4);
        wsplit_kernel<<<wgrid, 256, 0, sQ>>>(
            (const float4*)Wq, (const float4*)Wk, (const float4*)Wv,
            (const float4*)Wo, (__nv_bfloat162*)wh, (__nv_bfloat162*)wl, w4);
        // split_x on sW, concurrent with wsplit
        int n4 = MM * DD / 4;
        split_kernel<<<(n4 + 255) / 256, 256, 0, sW>>>(
            (const float4*)x, (__nv_bfloat162*)xh, (__nv_bfloat162*)xl, n4);
        cudaEventRecord(evX, sW);
        // bmask on sA (in-order before first attn)
        bmask_kernel<<<(LL * LL / 64) / 256, 256, 0, sA>>>(mask, bm);
        // QKV needs split_x too
        cudaStreamWaitEvent(sQ, evX, 0);
    }

    const int HB = BB / 2;                       // 4 batches per half
    dim3 qkv_grid(3 * DD / 128, HB * LL / 128);  // (24, 32)
    dim3 a_grid(LL / 128, HH, HB);               // (8, 16, 4)
    dim3 o_grid(DD / 128, HB * LL / 128);        // (8, 32)

    for (int hlf = 0; hlf < 2; hlf++) {
        const int mb = hlf * HB * LL;
        gemm_mma_kernel<1><<<qkv_grid, 256, GSMEM, sQ>>>(
            xh, xl, wh, wl, nullptr, qh, kh, kl, vh, SCALE_Q, mb);
        cudaEventRecord(evQ[hlf], sQ);

        cudaStreamWaitEvent(sA, evQ[hlf], 0);
        attn_mma_kernel<<<a_grid, 256, A_SMEM, sA>>>(
            qh, kh, kl, vh, bm, ah, al, hlf * HB);
        cudaEventRecord(evA[hlf], sA);

        cudaStreamWaitEvent(sW, evA[hlf], 0);
        gemm_mma_kernel<0><<<o_grid, 256, GSMEM, sW>>>(
            ah, al, wh + (size_t)3 * DD * DD, wl + (size_t)3 * DD * DD,
            out, nullptr, nullptr, nullptr, nullptr, 1.0f, mb);
    }

    // join
    cudaEventRecord(evJoin, sW);
    cudaStreamWaitEvent(0, evJoin, 0);
}

// round 17
// speedup vs baseline: 1.0518x; 1.0514x over previous
#include <cuda_runtime.h>
#include <cuda_bf16.h>
#include <cuda_fp16.h>
#include <math.h>
#include <stdint.h>

#define BB  8
#define LL  1024
#define DD  1024
#define HH  16
#define DHH 64
#define MM  (BB * LL)

typedef unsigned long long u64;

// ---------------- device-global scratch ----------------
__device__ __nv_bfloat16 g_xh[MM * DD], g_xl[MM * DD];
__device__ __nv_bfloat16 g_wh[4][DD * DD], g_wl[4][DD * DD];  // [Wq,Wk,Wv,Wo]
__device__ __half g_qh[MM * DD];
__device__ __half g_kh[MM * DD], g_kl[MM * DD];
__device__ __half g_vh[MM * DD];
__device__ __nv_bfloat16 g_ah[MM * DD], g_al[MM * DD];
__device__ u64 g_bmask[LL * LL / 64];

// ---------------- PTX helpers ----------------
__device__ __forceinline__ uint32_t s2u(const void* p) {
    uint32_t a;
    asm("{ .reg .u64 t; cvta.to.shared.u64 t, %1; cvt.u32.u64 %0, t; }"
        : "=r"(a) : "l"(p));
    return a;
}
__device__ __forceinline__ void cp16(uint32_t d, const void* s) {
    asm volatile("cp.async.cg.shared.global [%0], [%1], 16;" :: "r"(d), "l"(s));
}
__device__ __forceinline__ void cp_commit() {
    asm volatile("cp.async.commit_group;");
}
template <int N> __device__ __forceinline__ void cp_wait() {
    asm volatile("cp.async.wait_group %0;" :: "n"(N));
}
__device__ __forceinline__ void ldm4(uint32_t& r0, uint32_t& r1,
                                     uint32_t& r2, uint32_t& r3, uint32_t a) {
    asm volatile("ldmatrix.sync.aligned.m8n8.x4.shared.b16 {%0,%1,%2,%3}, [%4];"
                 : "=r"(r0), "=r"(r1), "=r"(r2), "=r"(r3) : "r"(a));
}
__device__ __forceinline__ void ldm4t(uint32_t& r0, uint32_t& r1,
                                      uint32_t& r2, uint32_t& r3, uint32_t a) {
    asm volatile("ldmatrix.sync.aligned.m8n8.x4.trans.shared.b16 {%0,%1,%2,%3}, [%4];"
                 : "=r"(r0), "=r"(r1), "=r"(r2), "=r"(r3) : "r"(a));
}
__device__ __forceinline__ void mma_bf16(float* c, const uint32_t* a,
                                         uint32_t b0, uint32_t b1) {
    asm volatile(
        "mma.sync.aligned.m16n8k16.row.col.f32.bf16.bf16.f32 "
        "{%0,%1,%2,%3}, {%4,%5,%6,%7}, {%8,%9}, {%0,%1,%2,%3};"
        : "+f"(c[0]), "+f"(c[1]), "+f"(c[2]), "+f"(c[3])
        : "r"(a[0]), "r"(a[1]), "r"(a[2]), "r"(a[3]), "r"(b0), "r"(b1));
}
__device__ __forceinline__ void mma_f16(float* c, uint32_t a0, uint32_t a1,
                                        uint32_t a2, uint32_t a3,
                                        uint32_t b0, uint32_t b1) {
    asm volatile(
        "mma.sync.aligned.m16n8k16.row.col.f32.f16.f16.f32 "
        "{%0,%1,%2,%3}, {%4,%5,%6,%7}, {%8,%9}, {%0,%1,%2,%3};"
        : "+f"(c[0]), "+f"(c[1]), "+f"(c[2]), "+f"(c[3])
        : "r"(a0), "r"(a1), "r"(a2), "r"(a3), "r"(b0), "r"(b1));
}
__device__ __forceinline__ float ex2f(float x) {
    float r;
    asm("ex2.approx.ftz.f32 %0, %1;" : "=f"(r) : "f"(x));
    return r;
}
__device__ __forceinline__ uint32_t packh2(float hi, float lo) {
    uint32_t r;
    asm("cvt.rn.f16x2.f32 %0, %1, %2;" : "=r"(r) : "f"(hi), "f"(lo));
    return r;
}
__device__ __forceinline__ float2 h2f2(uint32_t u) {
    __half2 h = *reinterpret_cast<__half2*>(&u);
    return __half22float2(h);
}

// ============================================================
// splits
// ============================================================
__global__ __launch_bounds__(256) void split_kernel(
    const float4* __restrict__ src,
    __nv_bfloat162* __restrict__ hi, __nv_bfloat162* __restrict__ lo, int n4)
{
    int i = blockIdx.x * blockDim.x + threadIdx.x;
    if (i >= n4) return;
    float4 v = src[i];
    __nv_bfloat16 hx = __float2bfloat16(v.x), hy = __float2bfloat16(v.y);
    __nv_bfloat16 hz = __float2bfloat16(v.z), hw = __float2bfloat16(v.w);
    hi[2 * i + 0] = __nv_bfloat162(hx, hy);
    hi[2 * i + 1] = __nv_bfloat162(hz, hw);
    lo[2 * i + 0] = __floats2bfloat162_rn(v.x - __bfloat162float(hx),
                                          v.y - __bfloat162float(hy));
    lo[2 * i + 1] = __floats2bfloat162_rn(v.z - __bfloat162float(hz),
                                          v.w - __bfloat162float(hw));
}

__global__ __launch_bounds__(256) void wsplit_kernel(
    const float4* __restrict__ w0, const float4* __restrict__ w1,
    const float4* __restrict__ w2, const float4* __restrict__ w3,
    __nv_bfloat162* __restrict__ hi, __nv_bfloat162* __restrict__ lo, int n4)
{
    int i = blockIdx.x * blockDim.x + threadIdx.x;
    if (i >= n4) return;
    int sel = blockIdx.y;
    const float4* src = (sel == 0) ? w0 : (sel == 1) ? w1 : (sel == 2) ? w2 : w3;
    size_t base = (size_t)sel * 2 * n4;
    float4 v = src[i];
    __nv_bfloat16 hx = __float2bfloat16(v.x), hy = __float2bfloat16(v.y);
    __nv_bfloat16 hz = __float2bfloat16(v.z), hw = __float2bfloat16(v.w);
    hi[base + 2 * i + 0] = __nv_bfloat162(hx, hy);
    hi[base + 2 * i + 1] = __nv_bfloat162(hz, hw);
    lo[base + 2 * i + 0] = __floats2bfloat162_rn(v.x - __bfloat162float(hx),
                                                 v.y - __bfloat162float(hy));
    lo[base + 2 * i + 1] = __floats2bfloat162_rn(v.z - __bfloat162float(hz),
                                                 v.w - __bfloat162float(hw));
}

// ============================================================
// mask -> 64-bit bitmask per (qb, kb, w, lane), bit = nt*4+j
// ============================================================
__global__ __launch_bounds__(256) void bmask_kernel(
    const float* __restrict__ mask, u64* __restrict__ bm)
{
    int idx = blockIdx.x * blockDim.x + threadIdx.x;
    if (idx >= LL * LL / 64) return;
    int lane = idx & 31, w = (idx >> 5) & 7, kb = (idx >> 8) & 7, qb = idx >> 11;
    u64 bits = 0;
#pragma unroll
    for (int e = 0; e < 64; e++) {
        int nt = e >> 2, j = e & 3;
        int q = qb * 128 + w * 16 + (lane >> 2) + 8 * (j >> 1);
        int k = kb * 128 + nt * 8 + (lane & 3) * 2 + (j & 1);
        if (mask[q * LL + k] != 0.f) bits |= (1ull << e);
    }
    bm[idx] = bits;
}

// ============================================================
// bf16-split GEMM (NT) — frozen r12 structure + m_base offset.
// MODE 0: fp32 out. MODE 1: fused QKV (Qh | Kh+Kl | Vh).
// ============================================================
#define BK 32
#define NKI (DD / BK)
#define MAT_B 8192
#define STG_B (4 * MAT_B)
#define OFF_AH 0
#define OFF_AL MAT_B
#define OFF_BH (2 * MAT_B)
#define OFF_BL (3 * MAT_B)
#define GSMEM (3 * STG_B)   // 98304

__device__ __forceinline__ uint32_t swz(int row, int c) {
    return (uint32_t)(row * 64 + ((c ^ (row & 3)) << 4));
}

__device__ __forceinline__ void g_load_stage(
    uint32_t sbase,
    const __nv_bfloat16* __restrict__ Ah, const __nv_bfloat16* __restrict__ Al,
    const __nv_bfloat16* __restrict__ Bh, const __nv_bfloat16* __restrict__ Bl,
    int m0, int n0, int k0, int tid)
{
    const int r1 = tid >> 2, r2 = r1 + 64, c = tid & 3;
    const int kc = k0 + c * 8;
    const size_t a1 = (size_t)(m0 + r1) * DD + kc;
    const size_t a2 = (size_t)(m0 + r2) * DD + kc;
    const size_t b1 = (size_t)(n0 + r1) * DD + kc;
    const size_t b2 = (size_t)(n0 + r2) * DD + kc;
    const uint32_t s1 = swz(r1, c), s2 = swz(r2, c);
    cp16(sbase + OFF_AH + s1, Ah + a1);
    cp16(sbase + OFF_AH + s2, Ah + a2);
    cp16(sbase + OFF_AL + s1, Al + a1);
    cp16(sbase + OFF_AL + s2, Al + a2);
    cp16(sbase + OFF_BH + s1, Bh + b1);
    cp16(sbase + OFF_BH + s2, Bh + b2);
    cp16(sbase + OFF_BL + s1, Bl + b1);
    cp16(sbase + OFF_BL + s2, Bl + b2);
}

template <int MODE>
__global__ __launch_bounds__(256, 2) void gemm_mma_kernel(
    const __nv_bfloat16* __restrict__ Ah, const __nv_bfloat16* __restrict__ Al,
    const __nv_bfloat16* __restrict__ Bh, const __nv_bfloat16* __restrict__ Bl,
    float* __restrict__ Cf,
    __half* __restrict__ Qh,
    __half* __restrict__ Kh, __half* __restrict__ Kl,
    __half* __restrict__ Vh,
    float scale_q, int m_base)
{
    extern __shared__ char smg[];
    const uint32_t sbase = s2u(smg);
    const int tid = threadIdx.x, wid = tid >> 5, lane = tid & 31;
    const int m0 = m_base + blockIdx.y * 128, n0 = blockIdx.x * 128;
    const int wm0 = (wid & 1) * 64, wn0 = (wid >> 1) * 32;

    float acc[4][4][4];
#pragma unroll
    for (int i = 0; i < 4; i++)
#pragma unroll
        for (int j = 0; j < 4; j++)
#pragma unroll
            for (int r = 0; r < 4; r++) acc[i][j][r] = 0.f;

    const int a_row_l = ((lane >> 3) & 1) * 8 + (lane & 7);
    const int a_cl = lane >> 4;
    const int b_row_l = (lane >> 4) * 8 + (lane & 7);
    const int b_cl = (lane >> 3) & 1;

    g_load_stage(sbase, Ah, Al, Bh, Bl, m0, n0, 0, tid);
    cp_commit();
    g_load_stage(sbase + STG_B, Ah, Al, Bh, Bl, m0, n0, BK, tid);
    cp_commit();

    int s_cur = 0, s_nxt = 2;
    for (int k = 0; k < NKI; k++) {
        cp_wait<1>();
        __syncthreads();
        if (k + 2 < NKI)
            g_load_stage(sbase + s_nxt * STG_B, Ah, Al, Bh, Bl,
                         m0, n0, (k + 2) * BK, tid);
        cp_commit();

        const uint32_t st = sbase + s_cur * STG_B;
#pragma unroll
        for (int kk = 0; kk < 2; kk++) {
            uint32_t ah[4][4], al[4][4], bh[2][4], bl[2][4];
#pragma unroll
            for (int mt = 0; mt < 4; mt++) {
                uint32_t off = swz(wm0 + mt * 16 + a_row_l, kk * 2 + a_cl);
                ldm4(ah[mt][0], ah[mt][1], ah[mt][2], ah[mt][3], st + OFF_AH + off);
                ldm4(al[mt][0], al[mt][1], al[mt][2], al[mt][3], st + OFF_AL + off);
            }
#pragma unroll
            for (int ng = 0; ng < 2; ng++) {
                uint32_t off = swz(wn0 + ng * 16 + b_row_l, kk * 2 + b_cl);
                ldm4(bh[ng][0], bh[ng][1], bh[ng][2], bh[ng][3], st + OFF_BH + off);
                ldm4(bl[ng][0], bl[ng][1], bl[ng][2], bl[ng][3], st + OFF_BL + off);
            }
#pragma unroll
            for (int mt = 0; mt < 4; mt++)
#pragma unroll
                for (int nt = 0; nt < 4; nt++) {
                    const int ng = nt >> 1, hb = (nt & 1) * 2;
                    mma_bf16(acc[mt][nt], ah[mt], bh[ng][hb], bh[ng][hb + 1]);
                    mma_bf16(acc[mt][nt], ah[mt], bl[ng][hb], bl[ng][hb + 1]);
                    mma_bf16(acc[mt][nt], al[mt], bh[ng][hb], bh[ng][hb + 1]);
                }
        }
        s_cur = (s_cur == 2) ? 0 : s_cur + 1;
        s_nxt = (s_nxt == 2) ? 0 : s_nxt + 1;
    }

    const int er = lane >> 2, ec = (lane & 3) * 2;
    if (MODE == 0) {
#pragma unroll
        for (int mt = 0; mt < 4; mt++)
#pragma unroll
            for (int nt = 0; nt < 4; nt++) {
                size_t i0 = (size_t)(m0 + wm0 + mt * 16 + er) * DD
                          + n0 + wn0 + nt * 8 + ec;
                size_t i1 = i0 + 8 * DD;
                *(float2*)(Cf + i0) = make_float2(acc[mt][nt][0], acc[mt][nt][1]);
                *(float2*)(Cf + i1) = make_float2(acc[mt][nt][2], acc[mt][nt][3]);
            }
    } else {
        const int which = n0 >> 10;                 // 0=Q, 1=K, 2=V
        __half* Ch = (which == 0) ? Qh : (which == 1) ? Kh : Vh;
        const float sc = (which == 0) ? scale_q : 1.0f;
        const int nc0 = n0 & 1023;
#pragma unroll
        for (int mt = 0; mt < 4; mt++)
#pragma unroll
            for (int nt = 0; nt < 4; nt++) {
                size_t i0 = (size_t)(m0 + wm0 + mt * 16 + er) * DD
                          + nc0 + wn0 + nt * 8 + ec;
                size_t i1 = i0 + 8 * DD;
                float v0 = acc[mt][nt][0] * sc, v1 = acc[mt][nt][1] * sc;
                float v2 = acc[mt][nt][2] * sc, v3 = acc[mt][nt][3] * sc;
                __half h0 = __float2half_rn(v0), h1 = __float2half_rn(v1);
                __half h2 = __float2half_rn(v2), h3 = __float2half_rn(v3);
                *(__half2*)(Ch + i0) = __half2(h0, h1);
                *(__half2*)(Ch + i1) = __half2(h2, h3);
                if (which == 1) {
                    *(__half2*)(Kl + i0) = __half2(
                        __float2half_rn(v0 - __half2float(h0)),
                        __float2half_rn(v1 - __half2float(h1)));
                    *(__half2*)(Kl + i1) = __half2(
                        __float2half_rn(v2 - __half2float(h2)),
                        __float2half_rn(v3 - __half2float(h3)));
                }
            }
    }
}

// ============================================================
// Tensor-core flash attention — frozen r12 structure + b_base.
// ============================================================
#define A_QH 0
#define A_ST 16384
#define A_STGB 49152
#define A_KH 0
#define A_KL 16384
#define A_VH 32768
#define A_SMEM (A_ST + 2 * A_STGB)   // 114688

__device__ __forceinline__ void a_load_q(
    uint32_t sb, const __half* qh, int b, int q0, int h, int tid)
{
    const int row = tid >> 1, cb = (tid & 1) * 4;
    const size_t base = ((size_t)(b * LL + q0 + row)) * DD + h * DHH;
#pragma unroll
    for (int c = 0; c < 4; c++) {
        int ch = cb + c;
        uint32_t dst = (uint32_t)(row * 128 + ((ch ^ (row & 7)) << 4));
        cp16(sb + A_QH + dst, qh + base + ch * 8);
    }
}
__device__ __forceinline__ void a_load_kv(
    uint32_t stg, const __half* kh, const __half* kl,
    const __half* vh, int b, int k0, int h, int tid)
{
    const int row = tid >> 1, cb = (tid & 1) * 4;
    const size_t base = ((size_t)(b * LL + k0 + row)) * DD + h * DHH;
#pragma unroll
    for (int c = 0; c < 4; c++) {
        int ch = cb + c;
        uint32_t dst = (uint32_t)(row * 128 + ((ch ^ (row & 7)) << 4));
        cp16(stg + A_KH + dst, kh + base + ch * 8);
        cp16(stg + A_KL + dst, kl + base + ch * 8);
        cp16(stg + A_VH + dst, vh + base + ch * 8);
    }
}

__global__ __launch_bounds__(256, 2) void attn_mma_kernel(
    const __half* __restrict__ qh,
    const __half* __restrict__ kh, const __half* __restrict__ kl,
    const __half* __restrict__ vh,
    const u64* __restrict__ bmask,
    __nv_bfloat16* __restrict__ ah, __nv_bfloat16* __restrict__ al,
    int b_base)
{
    extern __shared__ char sma[];
    const uint32_t sb = s2u(sma);
    const int tid = threadIdx.x, lane = tid & 31, w = tid >> 5;
    const int qb = blockIdx.x, h = blockIdx.y, b = b_base + blockIdx.z;
    const int q0 = qb * 128;

    a_load_q(sb, qh, b, q0, h, tid);
    a_load_kv(sb + A_ST, kh, kl, vh, b, 0, h, tid);
    cp_commit();
    cp_wait<0>();
    __syncthreads();

    uint32_t qf[4][4];
    {
        const int arow = w * 16 + ((lane >> 3) & 1) * 8 + (lane & 7);
        const int acl = lane >> 4;
#pragma unroll
        for (int kc = 0; kc < 4; kc++) {
            int ch = kc * 2 + acl;
            uint32_t off = (uint32_t)(arow * 128 + ((ch ^ (arow & 7)) << 4));
            ldm4(qf[kc][0], qf[kc][1], qf[kc][2], qf[kc][3], sb + A_QH + off);
        }
    }

    float acc_o[8][4];
#pragma unroll
    for (int i = 0; i < 8; i++)
#pragma unroll
        for (int j = 0; j < 4; j++) acc_o[i][j] = 0.f;
    float m0r = -1e30f, m1r = -1e30f, l0r = 0.f, l1r = 0.f;

    const u64* bmp = bmask + (size_t)qb * 2048 + w * 32 + lane;
    const int b_row_l = (lane >> 4) * 8 + (lane & 7);
    const int b_cl = (lane >> 3) & 1;
    const int v_row_l = ((lane >> 3) & 1) * 8 + (lane & 7);
    const int v_cl = lane >> 4;

    for (int kb = 0; kb < 8; kb++) {
        cp_wait<0>();
        __syncthreads();
        if (kb + 1 < 8) {
            a_load_kv(sb + A_ST + ((kb + 1) & 1) * A_STGB,
                      kh, kl, vh, b, (kb + 1) * 128, h, tid);
            cp_commit();
        }
        const uint32_t stg = sb + A_ST + (kb & 1) * A_STGB;

        float s[16][4];
#pragma unroll
        for (int i = 0; i < 16; i++)
#pragma unroll
            for (int j = 0; j < 4; j++) s[i][j] = 0.f;

#pragma unroll
        for (int g = 0; g < 8; g++)
#pragma unroll
            for (int kc = 0; kc < 4; kc++) {
                int row = g * 16 + b_row_l, ch = kc * 2 + b_cl;
                uint32_t off = (uint32_t)(row * 128 + ((ch ^ (row & 7)) << 4));
                uint32_t k4h[4], k4l[4];
                ldm4(k4h[0], k4h[1], k4h[2], k4h[3], stg + A_KH + off);
                ldm4(k4l[0], k4l[1], k4l[2], k4l[3], stg + A_KL + off);
                mma_f16(s[2*g],   qf[kc][0], qf[kc][1], qf[kc][2], qf[kc][3], k4h[0], k4h[1]);
                mma_f16(s[2*g+1], qf[kc][0], qf[kc][1], qf[kc][2], qf[kc][3], k4h[2], k4h[3]);
                mma_f16(s[2*g],   qf[kc][0], qf[kc][1], qf[kc][2], qf[kc][3], k4l[0], k4l[1]);
                mma_f16(s[2*g+1], qf[kc][0], qf[kc][1], qf[kc][2], qf[kc][3], k4l[2], k4l[3]);
            }

        const u64 bm = bmp[kb * 256];
        float mx0 = -1e30f, mx1 = -1e30f;
#pragma unroll
        for (int nt = 0; nt < 16; nt++) {
#pragma unroll
            for (int j = 0; j < 4; j++)
                if (!((bm >> (nt * 4 + j)) & 1ull)) s[nt][j] = -1e30f;
            mx0 = fmaxf(mx0, fmaxf(s[nt][0], s[nt][1]));
            mx1 = fmaxf(mx1, fmaxf(s[nt][2], s[nt][3]));
        }
        mx0 = fmaxf(mx0, __shfl_xor_sync(~0u, mx0, 1));
        mx0 = fmaxf(mx0, __shfl_xor_sync(~0u, mx0, 2));
        mx1 = fmaxf(mx1, __shfl_xor_sync(~0u, mx1, 1));
        mx1 = fmaxf(mx1, __shfl_xor_sync(~0u, mx1, 2));
        float mn0 = fmaxf(m0r, mx0), mn1 = fmaxf(m1r, mx1);
        float c0 = ex2f(m0r - mn0), c1 = ex2f(m1r - mn1);
        m0r = mn0; m1r = mn1;

        float ls0 = 0.f, ls1 = 0.f;
#pragma unroll
        for (int nt = 0; nt < 16; nt++) {
            s[nt][0] = ex2f(s[nt][0] - mn0);
            s[nt][1] = ex2f(s[nt][1] - mn0);
            s[nt][2] = ex2f(s[nt][2] - mn1);
            s[nt][3] = ex2f(s[nt][3] - mn1);
            ls0 += s[nt][0] + s[nt][1];
            ls1 += s[nt][2] + s[nt][3];
        }
        ls0 += __shfl_xor_sync(~0u, ls0, 1);
        ls0 += __shfl_xor_sync(~0u, ls0, 2);
        ls1 += __shfl_xor_sync(~0u, ls1, 1);
        ls1 += __shfl_xor_sync(~0u, ls1, 2);
        l0r = l0r * c0 + ls0;
        l1r = l1r * c1 + ls1;
#pragma unroll
        for (int i = 0; i < 8; i++) {
            acc_o[i][0] *= c0; acc_o[i][1] *= c0;
            acc_o[i][2] *= c1; acc_o[i][3] *= c1;
        }

#pragma unroll
        for (int kc = 0; kc < 8; kc++) {
            uint32_t ph0 = packh2(s[2*kc][1],   s[2*kc][0]);
            uint32_t ph1 = packh2(s[2*kc][3],   s[2*kc][2]);
            uint32_t ph2 = packh2(s[2*kc+1][1], s[2*kc+1][0]);
            uint32_t ph3 = packh2(s[2*kc+1][3], s[2*kc+1][2]);
            float2 f0 = h2f2(ph0), f1 = h2f2(ph1), f2 = h2f2(ph2), f3 = h2f2(ph3);
            uint32_t pl0 = packh2(s[2*kc][1] - f0.y,   s[2*kc][0] - f0.x);
            uint32_t pl1 = packh2(s[2*kc][3] - f1.y,   s[2*kc][2] - f1.x);
            uint32_t pl2 = packh2(s[2*kc+1][1] - f2.y, s[2*kc+1][0] - f2.x);
            uint32_t pl3 = packh2(s[2*kc+1][3] - f3.y, s[2*kc+1][2] - f3.x);
            int vrow = kc * 16 + v_row_l;
#pragma unroll
            for (int x4 = 0; x4 < 4; x4++) {
                int ch = x4 * 2 + v_cl;
                uint32_t off = (uint32_t)(vrow * 128 + ((ch ^ (vrow & 7)) << 4));
                uint32_t v4h[4];
                ldm4t(v4h[0], v4h[1], v4h[2], v4h[3], stg + A_VH + off);
                mma_f16(acc_o[2*x4],   ph0, ph1, ph2, ph3, v4h[0], v4h[1]);
                mma_f16(acc_o[2*x4+1], ph0, ph1, ph2, ph3, v4h[2], v4h[3]);
                mma_f16(acc_o[2*x4],   pl0, pl1, pl2, pl3, v4h[0], v4h[1]);
                mma_f16(acc_o[2*x4+1], pl0, pl1, pl2, pl3, v4h[2], v4h[3]);
            }
        }
    }

    const float inv0 = 1.f / l0r, inv1 = 1.f / l1r;
    const int r0 = q0 + w * 16 + (lane >> 2);
#pragma unroll
    for (int nt = 0; nt < 8; nt++) {
        int col = h * DHH + nt * 8 + (lane & 3) * 2;
        size_t i0 = (size_t)(b * LL + r0) * DD + col;
        size_t i1 = i0 + 8 * DD;
        float v0 = acc_o[nt][0] * inv0, v1 = acc_o[nt][1] * inv0;
        float v2 = acc_o[nt][2] * inv1, v3 = acc_o[nt][3] * inv1;
        __nv_bfloat16 h0 = __float2bfloat16(v0), h1 = __float2bfloat16(v1);
        __nv_bfloat16 h2 = __float2bfloat16(v2), h3 = __float2bfloat16(v3);
        *(__nv_bfloat162*)(ah + i0) = __nv_bfloat162(h0, h1);
        *(__nv_bfloat162*)(ah + i1) = __nv_bfloat162(h2, h3);
        *(__nv_bfloat162*)(al + i0) =
            __floats2bfloat162_rn(v0 - __bfloat162float(h0), v1 - __bfloat162float(h1));
        *(__nv_bfloat162*)(al + i1) =
            __floats2bfloat162_rn(v2 - __bfloat162float(h2), v3 - __bfloat162float(h3));
    }
}

// ============================================================
// Launch — r14 verbatim: serial prelude on stream 0, then
// half-split pipelined fork/join (3 equal-priority streams)
// ============================================================
extern "C" void kernel_launch(void* const* d_in, const int* in_sizes, int n_in,
                              void* d_out, int out_size)
{
    const float* x    = (const float*)d_in[0];
    const float* mask = (const float*)d_in[1];
    const float* Wk   = (const float*)d_in[2];
    const float* Wv   = (const float*)d_in[3];
    const float* Wq   = (const float*)d_in[4];
    const float* Wo   = (const float*)d_in[5];
    float* out = (float*)d_out;

    __nv_bfloat16 *xh, *xl, *ah, *al, *wh, *wl;
    __half *qh, *kh, *kl, *vh;
    u64* bm;
    cudaGetSymbolAddress((void**)&xh, g_xh);
    cudaGetSymbolAddress((void**)&xl, g_xl);
    cudaGetSymbolAddress((void**)&ah, g_ah);
    cudaGetSymbolAddress((void**)&al, g_al);
    cudaGetSymbolAddress((void**)&wh, g_wh);
    cudaGetSymbolAddress((void**)&wl, g_wl);
    cudaGetSymbolAddress((void**)&qh, g_qh);
    cudaGetSymbolAddress((void**)&kh, g_kh);
    cudaGetSymbolAddress((void**)&kl, g_kl);
    cudaGetSymbolAddress((void**)&vh, g_vh);
    cudaGetSymbolAddress((void**)&bm, g_bmask);

    static int init_done = 0;
    static cudaStream_t sQ, sA, sW;
    static cudaEvent_t evFork, evQ[2], evA[2], evJoin;
    if (!init_done) {
        cudaFuncSetAttribute(gemm_mma_kernel<0>,
                             cudaFuncAttributeMaxDynamicSharedMemorySize, GSMEM);
        cudaFuncSetAttribute(gemm_mma_kernel<1>,
                             cudaFuncAttributeMaxDynamicSharedMemorySize, GSMEM);
        cudaFuncSetAttribute(attn_mma_kernel,
                             cudaFuncAttributeMaxDynamicSharedMemorySize, A_SMEM);
        cudaStreamCreateWithFlags(&sQ, cudaStreamNonBlocking);
        cudaStreamCreateWithFlags(&sA, cudaStreamNonBlocking);
        cudaStreamCreateWithFlags(&sW, cudaStreamNonBlocking);
        cudaEventCreateWithFlags(&evFork, cudaEventDisableTiming);
        cudaEventCreateWithFlags(&evJoin, cudaEventDisableTiming);
        for (int hlf = 0; hlf < 2; hlf++) {
            cudaEventCreateWithFlags(&evQ[hlf], cudaEventDisableTiming);
            cudaEventCreateWithFlags(&evA[hlf], cudaEventDisableTiming);
        }
        init_done = 1;
    }

    const float SCALE_Q = 0.125f * 1.44269504088896341f;

    // prelude on the launch stream (serial — proven fastest, r15/r16 falsified parallel)
    {
        int n4 = MM * DD / 4;
        split_kernel<<<(n4 + 255) / 256, 256>>>(
            (const float4*)x, (__nv_bfloat162*)xh, (__nv_bfloat162*)xl, n4);
        int w4 = DD * DD / 4;
        dim3 wgrid((w4 + 255) / 256, 4);
        wsplit_kernel<<<wgrid, 256>>>(
            (const float4*)Wq, (const float4*)Wk, (const float4*)Wv,
            (const float4*)Wo, (__nv_bfloat162*)wh, (__nv_bfloat162*)wl, w4);
        bmask_kernel<<<(LL * LL / 64) / 256, 256>>>(mask, bm);
    }

    // fork
    cudaEventRecord(evFork, 0);
    cudaStreamWaitEvent(sQ, evFork, 0);
    cudaStreamWaitEvent(sA, evFork, 0);
    cudaStreamWaitEvent(sW, evFork, 0);

    const int HB = BB / 2;                       // 4 batches per half
    dim3 qkv_grid(3 * DD / 128, HB * LL / 128);  // (24, 32)
    dim3 a_grid(LL / 128, HH, HB);               // (8, 16, 4)
    dim3 o_grid(DD / 128, HB * LL / 128);        // (8, 32)

    for (int hlf = 0; hlf < 2; hlf++) {
        const int mb = hlf * HB * LL;
        gemm_mma_kernel<1><<<qkv_grid, 256, GSMEM, sQ>>>(
            xh, xl, wh, wl, nullptr, qh, kh, kl, vh, SCALE_Q, mb);
        cudaEventRecord(evQ[hlf], sQ);

        cudaStreamWaitEvent(sA, evQ[hlf], 0);
        attn_mma_kernel<<<a_grid, 256, A_SMEM, sA>>>(
            qh, kh, kl, vh, bm, ah, al, hlf * HB);
        cudaEventRecord(evA[hlf], sA);

        cudaStreamWaitEvent(sW, evA[hlf], 0);
        gemm_mma_kernel<0><<<o_grid, 256, GSMEM, sW>>>(
            ah, al, wh + (size_t)3 * DD * DD, wl + (size_t)3 * DD * DD,
            out, nullptr, nullptr, nullptr, nullptr, 1.0f, mb);
    }

    // join
    cudaEventRecord(evJoin, sW);
    cudaStreamWaitEvent(0, evJoin, 0);
}